// round 6
// baseline (speedup 1.0000x reference)
#include <cuda_runtime.h>
#include <cstdint>

#define NN 100000
#define NE 1600000
#define D  128
#define NL 3
#define NB_SCAN ((NN + 1023) / 1024)   // 98
#define NTILES ((NN + 127) / 128)      // 782
#define AST 130                         // As stride: conflict-free LDS.64 on rows

// Scratch (allocation-free rule: __device__ globals)
__device__ __align__(16) float g_buf0[(size_t)NN * D];
__device__ __align__(16) float g_buf1[(size_t)NN * D];
__device__ int g_deg[NN];
__device__ int g_rows[NN + 1];
__device__ int g_cursor[NN];
__device__ int g_bsum[NB_SCAN];
__device__ int g_boff[NB_SCAN];
__device__ int g_srcs[NE];
__device__ int g_tile_ctr[NL];

// ---------------------------------------------------------------------------
// packed f32x2 math (Blackwell FFMA2 — only reachable via PTX)
// ---------------------------------------------------------------------------
__device__ __forceinline__ unsigned long long pk2(float v) {
    unsigned long long r;
    asm("mov.b64 %0, {%1, %1};" : "=l"(r) : "f"(v));
    return r;
}
__device__ __forceinline__ void upk2(unsigned long long p, float& lo, float& hi) {
    asm("mov.b64 {%0, %1}, %2;" : "=f"(lo), "=f"(hi) : "l"(p));
}
__device__ __forceinline__ void fma2(unsigned long long& d,
                                     unsigned long long a,
                                     unsigned long long b) {
    asm("fma.rn.f32x2 %0, %1, %2, %0;" : "+l"(d) : "l"(a), "l"(b));
}

// ---------------------------------------------------------------------------
// CSR build: histogram -> scan -> fill
// ---------------------------------------------------------------------------
__global__ void hist_kernel(const int* __restrict__ dst, int* __restrict__ deg) {
    int i = blockIdx.x * blockDim.x + threadIdx.x;
    if (i < NE) atomicAdd(&deg[__ldg(dst + i)], 1);
}

__global__ void scan1_kernel(const int* __restrict__ deg, int* __restrict__ rows,
                             int* __restrict__ bsum) {
    __shared__ int ts[256];
    const int t = threadIdx.x;
    const int base = blockIdx.x * 1024 + t * 4;
    int v[4], s = 0;
    #pragma unroll
    for (int i = 0; i < 4; i++) {
        v[i] = (base + i < NN) ? deg[base + i] : 0;
        s += v[i];
    }
    ts[t] = s;
    __syncthreads();
    #pragma unroll
    for (int off = 1; off < 256; off <<= 1) {
        int x = (t >= off) ? ts[t - off] : 0;
        __syncthreads();
        ts[t] += x;
        __syncthreads();
    }
    int run = ts[t] - s;
    #pragma unroll
    for (int i = 0; i < 4; i++) {
        if (base + i < NN) rows[base + i] = run;
        run += v[i];
    }
    if (t == 255) bsum[blockIdx.x] = ts[255];
}

__global__ void scan2_kernel(const int* __restrict__ bsum, int* __restrict__ boff) {
    __shared__ int s[128];
    const int t = threadIdx.x;
    int orig = (t < NB_SCAN) ? bsum[t] : 0;
    s[t] = orig;
    __syncthreads();
    #pragma unroll
    for (int off = 1; off < 128; off <<= 1) {
        int x = (t >= off) ? s[t - off] : 0;
        __syncthreads();
        s[t] += x;
        __syncthreads();
    }
    if (t < NB_SCAN) boff[t] = s[t] - orig;
}

__global__ void scan3_kernel(int* __restrict__ rows, const int* __restrict__ boff) {
    int i = blockIdx.x * blockDim.x + threadIdx.x;
    if (i < NN) rows[i] += boff[i >> 10];
    if (i == 0) rows[NN] = NE;
}

__global__ void fill_kernel(const int* __restrict__ src, const int* __restrict__ dst,
                            int* __restrict__ cursor, int* __restrict__ srcs) {
    int i = blockIdx.x * blockDim.x + threadIdx.x;
    if (i < NE) {
        int d = __ldg(dst + i);
        int pos = atomicAdd(&cursor[d], 1);
        srcs[pos] = __ldg(src + i);
    }
}

// ---------------------------------------------------------------------------
// fused persistent layer kernel:
//   per tile (128 rows, grabbed from a dynamic queue):
//     gather: As[r] = x[n] + sum_{CSR} x[src]   (warp-per-row, lane-per-float4)
//     GEMM1 (FFMA2) -> relu+b1 -> As -> GEMM2 -> [relu]+b2 -> out
// 148 CTAs x 512 threads. Warp wd owns cols [wd*8, wd*8+8) in GEMMs.
// ---------------------------------------------------------------------------
__global__ __launch_bounds__(512, 1)
void layer_kernel(const float* __restrict__ xin,
                  const int* __restrict__ rows, const int* __restrict__ srcs,
                  const float* __restrict__ W1, const float* __restrict__ b1,
                  const float* __restrict__ W2, const float* __restrict__ b2,
                  float* __restrict__ out, int relu_out, int* __restrict__ ctr) {
    extern __shared__ float smem[];
    float* Ws1 = smem;                 // 128*128
    float* Ws2 = Ws1 + D * D;          // 128*128
    float* As  = Ws2 + D * D;          // 128*AST
    float* bs1 = As + 128 * AST;       // 128
    float* bs2 = bs1 + D;              // 128
    __shared__ int s_tile;

    const int tid  = threadIdx.x;
    const int lane = tid & 31;
    const int wd   = tid >> 5;         // 0..15

    // load weights + biases once (persistent)
    {
        const float4* w1g = (const float4*)W1;
        const float4* w2g = (const float4*)W2;
        float4* w1s = (float4*)Ws1;
        float4* w2s = (float4*)Ws2;
        for (int i = tid; i < D * D / 4; i += 512) {
            w1s[i] = __ldg(w1g + i);
            w2s[i] = __ldg(w2g + i);
        }
        if (tid < D) { bs1[tid] = __ldg(b1 + tid); bs2[tid] = __ldg(b2 + tid); }
    }

    const float4* x4 = (const float4*)xin;
    unsigned long long acc[4][4];

    auto gemm = [&](const float* __restrict__ Wsm) {
        #pragma unroll
        for (int r = 0; r < 4; r++)
            #pragma unroll
            for (int c = 0; c < 4; c++) acc[r][c] = 0ull;

        const float* arow = As + lane * AST;
        const float* wcol = Wsm + wd * 8;
        #pragma unroll 4
        for (int k = 0; k < D; k += 2) {
            ulonglong2 wA0 = *(const ulonglong2*)&wcol[k * D];
            ulonglong2 wA1 = *(const ulonglong2*)&wcol[k * D + 4];
            ulonglong2 wB0 = *(const ulonglong2*)&wcol[(k + 1) * D];
            ulonglong2 wB1 = *(const ulonglong2*)&wcol[(k + 1) * D + 4];
            unsigned long long wk0[4] = {wA0.x, wA0.y, wA1.x, wA1.y};
            unsigned long long wk1[4] = {wB0.x, wB0.y, wB1.x, wB1.y};
            #pragma unroll
            for (int r = 0; r < 4; r++) {
                float2 a = *(const float2*)&arow[r * 32 * AST + k];
                unsigned long long a0 = pk2(a.x);
                unsigned long long a1 = pk2(a.y);
                #pragma unroll
                for (int c = 0; c < 4; c++) {
                    fma2(acc[r][c], a0, wk0[c]);
                    fma2(acc[r][c], a1, wk1[c]);
                }
            }
        }
    };

    while (true) {
        if (tid == 0) s_tile = atomicAdd(ctr, 1);
        __syncthreads();                 // broadcast tile; also protects As reuse
        const int tile = s_tile;
        if (tile >= NTILES) break;
        const int row0 = tile * 128;

        // ---- fused gather into As: warp wd handles rows {wd, wd+16, ...} ----
        #pragma unroll
        for (int j = 0; j < 8; j++) {
            const int r = wd + j * 16;
            const int n = row0 + r;
            float4 acc4 = make_float4(0.f, 0.f, 0.f, 0.f);
            if (n < NN) {
                acc4 = __ldg(x4 + (size_t)n * 32 + lane);
                int e = __ldg(rows + n);
                const int end = __ldg(rows + n + 1);
                while (e < end) {
                    int cnt = min(32, end - e);
                    int sv = (lane < cnt) ? __ldg(srcs + e + lane) : 0;
                    int q = 0;
                    for (; q + 4 <= cnt; q += 4) {
                        int s0 = __shfl_sync(0xffffffff, sv, q + 0);
                        int s1 = __shfl_sync(0xffffffff, sv, q + 1);
                        int s2 = __shfl_sync(0xffffffff, sv, q + 2);
                        int s3 = __shfl_sync(0xffffffff, sv, q + 3);
                        float4 v0 = __ldg(x4 + (size_t)s0 * 32 + lane);
                        float4 v1 = __ldg(x4 + (size_t)s1 * 32 + lane);
                        float4 v2 = __ldg(x4 + (size_t)s2 * 32 + lane);
                        float4 v3 = __ldg(x4 + (size_t)s3 * 32 + lane);
                        acc4.x += v0.x; acc4.y += v0.y; acc4.z += v0.z; acc4.w += v0.w;
                        acc4.x += v1.x; acc4.y += v1.y; acc4.z += v1.z; acc4.w += v1.w;
                        acc4.x += v2.x; acc4.y += v2.y; acc4.z += v2.z; acc4.w += v2.w;
                        acc4.x += v3.x; acc4.y += v3.y; acc4.z += v3.z; acc4.w += v3.w;
                    }
                    for (; q < cnt; q++) {
                        int s = __shfl_sync(0xffffffff, sv, q);
                        float4 v = __ldg(x4 + (size_t)s * 32 + lane);
                        acc4.x += v.x; acc4.y += v.y; acc4.z += v.z; acc4.w += v.w;
                    }
                    e += cnt;
                }
            }
            float* p = &As[r * AST + lane * 4];
            ((float2*)p)[0] = make_float2(acc4.x, acc4.y);
            ((float2*)p)[1] = make_float2(acc4.z, acc4.w);
        }
        __syncthreads();

        // ---- GEMM1 ----
        gemm(Ws1);
        __syncthreads();

        // ---- epilogue 1: H = relu(acc + b1) -> As ----
        #pragma unroll
        for (int r = 0; r < 4; r++) {
            float* hrow = &As[(lane + r * 32) * AST + wd * 8];
            #pragma unroll
            for (int c = 0; c < 4; c++) {
                float lo, hi;
                upk2(acc[r][c], lo, hi);
                int col = wd * 8 + 2 * c;
                lo = fmaxf(lo + bs1[col], 0.f);
                hi = fmaxf(hi + bs1[col + 1], 0.f);
                ((float2*)hrow)[c] = make_float2(lo, hi);
            }
        }
        __syncthreads();

        // ---- GEMM2 ----
        gemm(Ws2);
        __syncthreads();

        // ---- epilogue 2: [relu](acc + b2) -> As (staging for coalesced store) ----
        #pragma unroll
        for (int r = 0; r < 4; r++) {
            float* orow = &As[(lane + r * 32) * AST + wd * 8];
            #pragma unroll
            for (int c = 0; c < 4; c++) {
                float lo, hi;
                upk2(acc[r][c], lo, hi);
                int col = wd * 8 + 2 * c;
                lo += bs2[col];
                hi += bs2[col + 1];
                if (relu_out) { lo = fmaxf(lo, 0.f); hi = fmaxf(hi, 0.f); }
                ((float2*)orow)[c] = make_float2(lo, hi);
            }
        }
        __syncthreads();

        // ---- coalesced global store ----
        for (int i = tid; i < 128 * 32; i += 512) {
            int r = i >> 5;
            int c = i & 31;
            int gr = row0 + r;
            if (gr < NN) {
                const float* p = &As[r * AST + c * 4];
                float2 u = ((const float2*)p)[0];
                float2 w = ((const float2*)p)[1];
                ((float4*)(out + (size_t)gr * D))[c] = make_float4(u.x, u.y, w.x, w.y);
            }
        }
    }
}

// ---------------------------------------------------------------------------
// launch
// ---------------------------------------------------------------------------
extern "C" void kernel_launch(void* const* d_in, const int* in_sizes, int n_in,
                              void* d_out, int out_size) {
    const float* x  = (const float*)d_in[0];
    const int*   ei = (const int*)d_in[1];
    const float* W1 = (const float*)d_in[2];
    const float* b1 = (const float*)d_in[3];
    const float* W2 = (const float*)d_in[4];
    const float* b2 = (const float*)d_in[5];
    float* out = (float*)d_out;

    const int* src = ei;
    const int* dst = ei + NE;

    float *p_buf0, *p_buf1;
    int *p_deg, *p_rows, *p_cursor, *p_bsum, *p_boff, *p_srcs, *p_ctr;
    cudaGetSymbolAddress((void**)&p_buf0,   g_buf0);
    cudaGetSymbolAddress((void**)&p_buf1,   g_buf1);
    cudaGetSymbolAddress((void**)&p_deg,    g_deg);
    cudaGetSymbolAddress((void**)&p_rows,   g_rows);
    cudaGetSymbolAddress((void**)&p_cursor, g_cursor);
    cudaGetSymbolAddress((void**)&p_bsum,   g_bsum);
    cudaGetSymbolAddress((void**)&p_boff,   g_boff);
    cudaGetSymbolAddress((void**)&p_srcs,   g_srcs);
    cudaGetSymbolAddress((void**)&p_ctr,    g_tile_ctr);

    const size_t smem_bytes = (size_t)(2 * D * D + 128 * AST + 2 * D) * sizeof(float);
    cudaFuncSetAttribute(layer_kernel, cudaFuncAttributeMaxDynamicSharedMemorySize,
                         (int)smem_bytes);

    // ---- CSR build (once per call) ----
    cudaMemsetAsync(p_deg, 0, NN * sizeof(int));
    cudaMemsetAsync(p_ctr, 0, NL * sizeof(int));
    hist_kernel<<<(NE + 255) / 256, 256>>>(dst, p_deg);
    scan1_kernel<<<NB_SCAN, 256>>>(p_deg, p_rows, p_bsum);
    scan2_kernel<<<1, 128>>>(p_bsum, p_boff);
    scan3_kernel<<<(NN + 255) / 256, 256>>>(p_rows, p_boff);
    cudaMemcpyAsync(p_cursor, p_rows, NN * sizeof(int), cudaMemcpyDeviceToDevice);
    fill_kernel<<<(NE + 255) / 256, 256>>>(src, dst, p_cursor, p_srcs);

    // ---- fused layers ----
    const float* lin[3]  = {x, p_buf0, p_buf1};
    float*       lout[3] = {p_buf0, p_buf1, out};

    for (int l = 0; l < NL; l++) {
        layer_kernel<<<148, 512, smem_bytes>>>(
            lin[l], p_rows, p_srcs,
            W1 + (size_t)l * D * D, b1 + (size_t)l * D,
            W2 + (size_t)l * D * D, b2 + (size_t)l * D,
            lout[l], (l < NL - 1) ? 1 : 0, p_ctr + l);
    }
    (void)in_sizes; (void)n_in; (void)out_size;
}

// round 7
// speedup vs baseline: 1.8696x; 1.8696x over previous
#include <cuda_runtime.h>
#include <cuda_bf16.h>
#include <cstdint>
#include <cstring>

#define NN 100000
#define NE 1600000
#define D  128
#define NL 3
#define NB_SCAN ((NN + 1023) / 1024)   // 98
#define NTILES ((NN + 127) / 128)      // 782

// Scratch (allocation-free rule: __device__ globals)
__device__ __align__(16) float g_buf0[(size_t)NN * D];
__device__ __align__(16) float g_buf1[(size_t)NN * D];
__device__ __align__(16) float g_h   [(size_t)NN * D];
__device__ int g_deg[NN];
__device__ int g_rows[NN + 1];
__device__ int g_cursor[NN];
__device__ int g_bsum[NB_SCAN];
__device__ int g_boff[NB_SCAN];
__device__ int g_srcs[NE];
__device__ int g_tile_ctr[NL];

// ---------------------------------------------------------------------------
// smem layout for MLP kernel (bytes). WST: bf16 row stride 136 (=272B; rows of
// an 8x8 ldmatrix land in 8 distinct 16B groups -> conflict-free LDSM)
// ---------------------------------------------------------------------------
#define WST 136
#define WSZ (128 * WST * 2)            // 34816 B per 128x128 bf16 image
#define OFF_W1HI 0
#define OFF_W1LO (OFF_W1HI + WSZ)
#define OFF_W2HI (OFF_W1LO + WSZ)
#define OFF_W2LO (OFF_W2HI + WSZ)
#define OFF_AHI  (OFF_W2LO + WSZ)
#define OFF_ALO  (OFF_AHI + WSZ)
#define OFF_BS1  (OFF_ALO + WSZ)       // 128 floats
#define OFF_BS2  (OFF_BS1 + 512)
#define SMEM_TOT (OFF_BS2 + 512)       // 209920 B

// ---------------------------------------------------------------------------
// helpers
// ---------------------------------------------------------------------------
__device__ __forceinline__ uint32_t smem_u32(const void* p) {
    uint32_t a;
    asm("{ .reg .u64 t; cvta.to.shared.u64 t, %1; cvt.u32.u64 %0, t; }"
        : "=r"(a) : "l"(p));
    return a;
}
// pack two floats to bf16x2 (lo in low half); also return the rounded floats
__device__ __forceinline__ uint32_t pack2bf(float lo, float hi,
                                            float& flo, float& fhi) {
    __nv_bfloat162 p = __floats2bfloat162_rn(lo, hi);
    flo = __low2float(p);
    fhi = __high2float(p);
    uint32_t r;
    memcpy(&r, &p, 4);
    return r;
}
__device__ __forceinline__ uint32_t pack2bf_only(float lo, float hi) {
    __nv_bfloat162 p = __floats2bfloat162_rn(lo, hi);
    uint32_t r;
    memcpy(&r, &p, 4);
    return r;
}
__device__ __forceinline__ void ldsm4(uint32_t* r, uint32_t addr) {
    asm volatile("ldmatrix.sync.aligned.m8n8.x4.shared.b16 {%0,%1,%2,%3}, [%4];"
                 : "=r"(r[0]), "=r"(r[1]), "=r"(r[2]), "=r"(r[3]) : "r"(addr));
}
__device__ __forceinline__ void ldsm4t(uint32_t* r, uint32_t addr) {
    asm volatile("ldmatrix.sync.aligned.m8n8.x4.trans.shared.b16 {%0,%1,%2,%3}, [%4];"
                 : "=r"(r[0]), "=r"(r[1]), "=r"(r[2]), "=r"(r[3]) : "r"(addr));
}
__device__ __forceinline__ void mma_bf16(float* c, const uint32_t* a,
                                         const uint32_t* b) {
    asm volatile("mma.sync.aligned.m16n8k16.row.col.f32.bf16.bf16.f32 "
                 "{%0,%1,%2,%3}, {%4,%5,%6,%7}, {%8,%9}, {%0,%1,%2,%3};"
                 : "+f"(c[0]), "+f"(c[1]), "+f"(c[2]), "+f"(c[3])
                 : "r"(a[0]), "r"(a[1]), "r"(a[2]), "r"(a[3]),
                   "r"(b[0]), "r"(b[1]));
}

// ---------------------------------------------------------------------------
// CSR build: histogram -> scan -> fill
// ---------------------------------------------------------------------------
__global__ void hist_kernel(const int* __restrict__ dst, int* __restrict__ deg) {
    int i = blockIdx.x * blockDim.x + threadIdx.x;
    if (i < NE) atomicAdd(&deg[__ldg(dst + i)], 1);
}

__global__ void scan1_kernel(const int* __restrict__ deg, int* __restrict__ rows,
                             int* __restrict__ bsum) {
    __shared__ int ts[256];
    const int t = threadIdx.x;
    const int base = blockIdx.x * 1024 + t * 4;
    int v[4], s = 0;
    #pragma unroll
    for (int i = 0; i < 4; i++) {
        v[i] = (base + i < NN) ? deg[base + i] : 0;
        s += v[i];
    }
    ts[t] = s;
    __syncthreads();
    #pragma unroll
    for (int off = 1; off < 256; off <<= 1) {
        int x = (t >= off) ? ts[t - off] : 0;
        __syncthreads();
        ts[t] += x;
        __syncthreads();
    }
    int run = ts[t] - s;
    #pragma unroll
    for (int i = 0; i < 4; i++) {
        if (base + i < NN) rows[base + i] = run;
        run += v[i];
    }
    if (t == 255) bsum[blockIdx.x] = ts[255];
}

__global__ void scan2_kernel(const int* __restrict__ bsum, int* __restrict__ boff) {
    __shared__ int s[128];
    const int t = threadIdx.x;
    int orig = (t < NB_SCAN) ? bsum[t] : 0;
    s[t] = orig;
    __syncthreads();
    #pragma unroll
    for (int off = 1; off < 128; off <<= 1) {
        int x = (t >= off) ? s[t - off] : 0;
        __syncthreads();
        s[t] += x;
        __syncthreads();
    }
    if (t < NB_SCAN) boff[t] = s[t] - orig;
}

__global__ void scan3_kernel(int* __restrict__ rows, const int* __restrict__ boff) {
    int i = blockIdx.x * blockDim.x + threadIdx.x;
    if (i < NN) rows[i] += boff[i >> 10];
    if (i == 0) rows[NN] = NE;
}

__global__ void fill_kernel(const int* __restrict__ src, const int* __restrict__ dst,
                            int* __restrict__ cursor, int* __restrict__ srcs) {
    int i = blockIdx.x * blockDim.x + threadIdx.x;
    if (i < NE) {
        int d = __ldg(dst + i);
        int pos = atomicAdd(&cursor[d], 1);
        srcs[pos] = __ldg(src + i);
    }
}

// ---------------------------------------------------------------------------
// pull-mode gather-sum: one warp per node (R5-proven, ~L2 roofline)
// ---------------------------------------------------------------------------
__global__ __launch_bounds__(256)
void gather_kernel(const float* __restrict__ x, const int* __restrict__ rows,
                   const int* __restrict__ srcs, float* __restrict__ h) {
    const int n = (blockIdx.x * blockDim.x + threadIdx.x) >> 5;
    if (n >= NN) return;
    const int lane = threadIdx.x & 31;
    const float4* x4 = (const float4*)x;
    float4 acc = __ldg(x4 + (size_t)n * 32 + lane);
    int e = __ldg(rows + n);
    const int end = __ldg(rows + n + 1);
    while (e < end) {
        int cnt = min(32, end - e);
        int sv = (lane < cnt) ? __ldg(srcs + e + lane) : 0;
        int j = 0;
        for (; j + 4 <= cnt; j += 4) {
            int s0 = __shfl_sync(0xffffffff, sv, j + 0);
            int s1 = __shfl_sync(0xffffffff, sv, j + 1);
            int s2 = __shfl_sync(0xffffffff, sv, j + 2);
            int s3 = __shfl_sync(0xffffffff, sv, j + 3);
            float4 v0 = __ldg(x4 + (size_t)s0 * 32 + lane);
            float4 v1 = __ldg(x4 + (size_t)s1 * 32 + lane);
            float4 v2 = __ldg(x4 + (size_t)s2 * 32 + lane);
            float4 v3 = __ldg(x4 + (size_t)s3 * 32 + lane);
            acc.x += v0.x; acc.y += v0.y; acc.z += v0.z; acc.w += v0.w;
            acc.x += v1.x; acc.y += v1.y; acc.z += v1.z; acc.w += v1.w;
            acc.x += v2.x; acc.y += v2.y; acc.z += v2.z; acc.w += v2.w;
            acc.x += v3.x; acc.y += v3.y; acc.z += v3.z; acc.w += v3.w;
        }
        for (; j < cnt; j++) {
            int s = __shfl_sync(0xffffffff, sv, j);
            float4 v = __ldg(x4 + (size_t)s * 32 + lane);
            acc.x += v.x; acc.y += v.y; acc.z += v.z; acc.w += v.w;
        }
        e += cnt;
    }
    ((float4*)h)[(size_t)n * 32 + lane] = acc;
}

// ---------------------------------------------------------------------------
// persistent tensor-core MLP: out = [relu]( relu(h @ W1 + b1) @ W2 + b2 )
// bf16 hi/lo 3-term split, mma.sync.m16n8k16, fp32 accumulate.
// 148 CTAs x 512 threads (16 warps, 4x4), warp owns 32x32 output block.
// ---------------------------------------------------------------------------
__global__ __launch_bounds__(512, 1)
void mlp_mma_kernel(const float* __restrict__ hin,
                    const float* __restrict__ W1g, const float* __restrict__ b1,
                    const float* __restrict__ W2g, const float* __restrict__ b2,
                    float* __restrict__ out, int relu_out, int* __restrict__ ctr) {
    extern __shared__ char smem[];
    const uint32_t sb = smem_u32(smem);
    const int tid  = threadIdx.x;
    const int lane = tid & 31;
    const int wid  = tid >> 5;
    const int wm   = wid >> 2;     // 0..3 : 32-row block
    const int wn   = wid & 3;      // 0..3 : 32-col block
    __shared__ int s_tile;

    // ---- convert weights fp32 -> hi/lo bf16 images (once, persistent) ----
    for (int i = tid; i < 4096; i += 512) {
        int k = i >> 5, c4 = (i & 31) * 4;
        uint32_t doff = (uint32_t)(k * WST + c4) * 2;
        {
            float4 v = __ldg((const float4*)(W1g + (size_t)k * D + c4));
            float f0, f1, f2, f3;
            uint32_t h0 = pack2bf(v.x, v.y, f0, f1);
            uint32_t h1 = pack2bf(v.z, v.w, f2, f3);
            uint32_t l0 = pack2bf_only(v.x - f0, v.y - f1);
            uint32_t l1 = pack2bf_only(v.z - f2, v.w - f3);
            *(uint2*)(smem + OFF_W1HI + doff) = make_uint2(h0, h1);
            *(uint2*)(smem + OFF_W1LO + doff) = make_uint2(l0, l1);
        }
        {
            float4 v = __ldg((const float4*)(W2g + (size_t)k * D + c4));
            float f0, f1, f2, f3;
            uint32_t h0 = pack2bf(v.x, v.y, f0, f1);
            uint32_t h1 = pack2bf(v.z, v.w, f2, f3);
            uint32_t l0 = pack2bf_only(v.x - f0, v.y - f1);
            uint32_t l1 = pack2bf_only(v.z - f2, v.w - f3);
            *(uint2*)(smem + OFF_W2HI + doff) = make_uint2(h0, h1);
            *(uint2*)(smem + OFF_W2LO + doff) = make_uint2(l0, l1);
        }
    }
    if (tid < D) {
        ((float*)(smem + OFF_BS1))[tid] = __ldg(b1 + tid);
        ((float*)(smem + OFF_BS2))[tid] = __ldg(b2 + tid);
    }

    const float* bs1f = (const float*)(smem + OFF_BS1);
    const float* bs2f = (const float*)(smem + OFF_BS2);
    const int tg = lane >> 2;      // 0..7 row-in-frag
    const int t4 = lane & 3;       // col pair

    float c[2][4][4];

    auto gemm = [&](uint32_t whi, uint32_t wlo) {
        #pragma unroll
        for (int mt = 0; mt < 2; mt++)
            #pragma unroll
            for (int ns = 0; ns < 4; ns++)
                #pragma unroll
                for (int q = 0; q < 4; q++) c[mt][ns][q] = 0.f;

        const int arow = lane & 15;
        const int asel = (lane >> 4) * 8;
        #pragma unroll
        for (int kc = 0; kc < 8; kc++) {
            uint32_t ahi[2][4], alo[2][4], bhi[2][4], blo[2][4];
            #pragma unroll
            for (int mt = 0; mt < 2; mt++) {
                uint32_t off = (uint32_t)((wm * 32 + mt * 16 + arow) * WST +
                                          kc * 16 + asel) * 2;
                ldsm4(ahi[mt], sb + OFF_AHI + off);
                ldsm4(alo[mt], sb + OFF_ALO + off);
            }
            #pragma unroll
            for (int g = 0; g < 2; g++) {
                uint32_t off = (uint32_t)((kc * 16 + arow) * WST +
                                          wn * 32 + g * 16 + asel) * 2;
                ldsm4t(bhi[g], sb + whi + off);
                ldsm4t(blo[g], sb + wlo + off);
            }
            #pragma unroll
            for (int mt = 0; mt < 2; mt++)
                #pragma unroll
                for (int ns = 0; ns < 4; ns++) {
                    const uint32_t* bh = &bhi[ns >> 1][(ns & 1) * 2];
                    const uint32_t* bl = &blo[ns >> 1][(ns & 1) * 2];
                    mma_bf16(c[mt][ns], ahi[mt], bh);
                    mma_bf16(c[mt][ns], ahi[mt], bl);
                    mma_bf16(c[mt][ns], alo[mt], bh);
                }
        }
    };

    while (true) {
        if (tid == 0) s_tile = atomicAdd(ctr, 1);
        __syncthreads();               // broadcast + protect A vs prev GEMM2 reads
        const int tile = s_tile;
        if (tile >= NTILES) break;
        const int row0 = tile * 128;

        // ---- A tile: fp32 -> hi/lo bf16 ----
        for (int i = tid; i < 4096; i += 512) {
            int r = i >> 5, c4 = (i & 31) * 4;
            int gr = row0 + r;
            float4 v = make_float4(0.f, 0.f, 0.f, 0.f);
            if (gr < NN) v = __ldg((const float4*)(hin + (size_t)gr * D + c4));
            float f0, f1, f2, f3;
            uint32_t h0 = pack2bf(v.x, v.y, f0, f1);
            uint32_t h1 = pack2bf(v.z, v.w, f2, f3);
            uint32_t l0 = pack2bf_only(v.x - f0, v.y - f1);
            uint32_t l1 = pack2bf_only(v.z - f2, v.w - f3);
            uint32_t doff = (uint32_t)(r * WST + c4) * 2;
            *(uint2*)(smem + OFF_AHI + doff) = make_uint2(h0, h1);
            *(uint2*)(smem + OFF_ALO + doff) = make_uint2(l0, l1);
        }
        __syncthreads();

        // ---- GEMM1 ----
        gemm(OFF_W1HI, OFF_W1LO);
        __syncthreads();               // all warps done reading A

        // ---- epilogue 1: H = relu(C + b1) -> hi/lo back into A buffers ----
        #pragma unroll
        for (int mt = 0; mt < 2; mt++) {
            const int r0 = wm * 32 + mt * 16 + tg;
            #pragma unroll
            for (int ns = 0; ns < 4; ns++) {
                const int col = wn * 32 + ns * 8 + t4 * 2;
                const float bb0 = bs1f[col], bb1 = bs1f[col + 1];
                float v00 = fmaxf(c[mt][ns][0] + bb0, 0.f);
                float v01 = fmaxf(c[mt][ns][1] + bb1, 0.f);
                float v10 = fmaxf(c[mt][ns][2] + bb0, 0.f);
                float v11 = fmaxf(c[mt][ns][3] + bb1, 0.f);
                float f0, f1;
                uint32_t doff0 = (uint32_t)(r0 * WST + col) * 2;
                uint32_t doff1 = (uint32_t)((r0 + 8) * WST + col) * 2;
                uint32_t hp = pack2bf(v00, v01, f0, f1);
                uint32_t lp = pack2bf_only(v00 - f0, v01 - f1);
                *(uint32_t*)(smem + OFF_AHI + doff0) = hp;
                *(uint32_t*)(smem + OFF_ALO + doff0) = lp;
                hp = pack2bf(v10, v11, f0, f1);
                lp = pack2bf_only(v10 - f0, v11 - f1);
                *(uint32_t*)(smem + OFF_AHI + doff1) = hp;
                *(uint32_t*)(smem + OFF_ALO + doff1) = lp;
            }
        }
        __syncthreads();

        // ---- GEMM2 ----
        gemm(OFF_W2HI, OFF_W2LO);

        // ---- epilogue 2: out = [relu](C + b2), direct fp32 stores ----
        #pragma unroll
        for (int mt = 0; mt < 2; mt++) {
            const int r0 = row0 + wm * 32 + mt * 16 + tg;
            #pragma unroll
            for (int ns = 0; ns < 4; ns++) {
                const int col = wn * 32 + ns * 8 + t4 * 2;
                const float bb0 = bs2f[col], bb1 = bs2f[col + 1];
                float v00 = c[mt][ns][0] + bb0;
                float v01 = c[mt][ns][1] + bb1;
                float v10 = c[mt][ns][2] + bb0;
                float v11 = c[mt][ns][3] + bb1;
                if (relu_out) {
                    v00 = fmaxf(v00, 0.f); v01 = fmaxf(v01, 0.f);
                    v10 = fmaxf(v10, 0.f); v11 = fmaxf(v11, 0.f);
                }
                if (r0 < NN)
                    *(float2*)(out + (size_t)r0 * D + col) = make_float2(v00, v01);
                if (r0 + 8 < NN)
                    *(float2*)(out + (size_t)(r0 + 8) * D + col) = make_float2(v10, v11);
            }
        }
    }
}

// ---------------------------------------------------------------------------
// launch
// ---------------------------------------------------------------------------
extern "C" void kernel_launch(void* const* d_in, const int* in_sizes, int n_in,
                              void* d_out, int out_size) {
    const float* x  = (const float*)d_in[0];
    const int*   ei = (const int*)d_in[1];
    const float* W1 = (const float*)d_in[2];
    const float* b1 = (const float*)d_in[3];
    const float* W2 = (const float*)d_in[4];
    const float* b2 = (const float*)d_in[5];
    float* out = (float*)d_out;

    const int* src = ei;
    const int* dst = ei + NE;

    float *p_buf0, *p_buf1, *p_h;
    int *p_deg, *p_rows, *p_cursor, *p_bsum, *p_boff, *p_srcs, *p_ctr;
    cudaGetSymbolAddress((void**)&p_buf0,   g_buf0);
    cudaGetSymbolAddress((void**)&p_buf1,   g_buf1);
    cudaGetSymbolAddress((void**)&p_h,      g_h);
    cudaGetSymbolAddress((void**)&p_deg,    g_deg);
    cudaGetSymbolAddress((void**)&p_rows,   g_rows);
    cudaGetSymbolAddress((void**)&p_cursor, g_cursor);
    cudaGetSymbolAddress((void**)&p_bsum,   g_bsum);
    cudaGetSymbolAddress((void**)&p_boff,   g_boff);
    cudaGetSymbolAddress((void**)&p_srcs,   g_srcs);
    cudaGetSymbolAddress((void**)&p_ctr,    g_tile_ctr);

    cudaFuncSetAttribute(mlp_mma_kernel, cudaFuncAttributeMaxDynamicSharedMemorySize,
                         SMEM_TOT);

    // ---- CSR build (once per call) ----
    cudaMemsetAsync(p_deg, 0, NN * sizeof(int));
    cudaMemsetAsync(p_ctr, 0, NL * sizeof(int));
    hist_kernel<<<(NE + 255) / 256, 256>>>(dst, p_deg);
    scan1_kernel<<<NB_SCAN, 256>>>(p_deg, p_rows, p_bsum);
    scan2_kernel<<<1, 128>>>(p_bsum, p_boff);
    scan3_kernel<<<(NN + 255) / 256, 256>>>(p_rows, p_boff);
    cudaMemcpyAsync(p_cursor, p_rows, NN * sizeof(int), cudaMemcpyDeviceToDevice);
    fill_kernel<<<(NE + 255) / 256, 256>>>(src, dst, p_cursor, p_srcs);

    // ---- layers ----
    const int gat_blocks = (NN * 32 + 255) / 256;

    const float* lin[3]  = {x, p_buf0, p_buf1};
    float*       lout[3] = {p_buf0, p_buf1, out};

    for (int l = 0; l < NL; l++) {
        gather_kernel<<<gat_blocks, 256>>>(lin[l], p_rows, p_srcs, p_h);
        mlp_mma_kernel<<<148, 512, SMEM_TOT>>>(
            p_h,
            W1 + (size_t)l * D * D, b1 + (size_t)l * D,
            W2 + (size_t)l * D * D, b2 + (size_t)l * D,
            lout[l], (l < NL - 1) ? 1 : 0, p_ctr + l);
    }
    (void)in_sizes; (void)n_in; (void)out_size;
}